// round 14
// baseline (speedup 1.0000x reference)
#include <cuda_runtime.h>
#include <cuda_fp16.h>
#include <cstdint>

#define BB 4
#define TT 4096
#define CC 1024
#define MT (BB*TT)          // 16384 rows
#define CHUNK 32
#define NCH (TT/CHUNK)      // 128 chunks

// ---------------- scratch (no cudaMalloc allowed) ----------------
__device__ __align__(128) __half g_xk[MT*CC];
__device__ __align__(128) __half g_xv[MT*CC];
__device__ __align__(128) __half g_xr[MT*CC];
__device__ __align__(128) __half g_rw[MT*CC];
__device__ __align__(128) __half g_w[4*CC*CC];
__device__ __align__(128) __half g_k [MT*CC];
__device__ __align__(128) __half g_v [MT*CC];
__device__ __align__(128) __half g_sr[MT*CC];
__device__ float g_cA[BB*NCH*CC];
__device__ float g_cB[BB*NCH*CC];
__device__ float g_pA[BB*NCH*CC];
__device__ float g_pB[BB*NCH*CC];
__device__ int g_ctr[4];   // tile counters (memset to 0 each replay)

// ================= fast math =================
__device__ __forceinline__ float fast_rcp(float d) {
    float x = __int_as_float(0x7EF311C3 - __float_as_int(d));
    x = x * fmaf(-d, x, 2.0f);
    x = x * fmaf(-d, x, 2.0f);
    return x;
}

__device__ __forceinline__ float fast_exp(float x) {   // FMA-pipe exp (GEMM epilogue only)
    float t = fmaf(x, 1.4426950408889634f, 12582912.0f);
    float n = t - 12582912.0f;
    float r = fmaf(x, 1.4426950408889634f, -n);
    float p = 1.3333558146e-3f;
    p = fmaf(p, r, 9.6181291076e-3f);
    p = fmaf(p, r, 5.5504108664e-2f);
    p = fmaf(p, r, 2.4022650696e-1f);
    p = fmaf(p, r, 6.9314718056e-1f);
    p = fmaf(p, r, 1.0f);
    int ei = (int)n;
    if (ei < -126) return 0.0f;
    if (ei > 127) ei = 127;
    return p * __int_as_float((ei + 127) << 23);
}

__device__ __forceinline__ float fast_sigmoid(float x) {
    return fast_rcp(1.0f + fast_exp(-x));
}

// ================= PTX helpers (arch-generic only) =================
__device__ __forceinline__ uint32_t smem_u32(const void* p) {
    uint32_t a;
    asm("{ .reg .u64 t; cvta.to.shared.u64 t, %1; cvt.u32.u64 %0, t; }" : "=r"(a) : "l"(p));
    return a;
}

__device__ __forceinline__ void ldmx4(uint32_t r[4], uint32_t addr) {
    asm volatile("ldmatrix.sync.aligned.m8n8.x4.shared.b16 {%0,%1,%2,%3}, [%4];"
        : "=r"(r[0]), "=r"(r[1]), "=r"(r[2]), "=r"(r[3]) : "r"(addr));
}

__device__ __forceinline__ void mma_fp16(float c[4], const uint32_t a[4],
                                         uint32_t b0, uint32_t b1) {
    asm volatile(
        "mma.sync.aligned.m16n8k16.row.col.f32.f16.f16.f32 "
        "{%0,%1,%2,%3}, {%4,%5,%6,%7}, {%8,%9}, {%0,%1,%2,%3};"
        : "+f"(c[0]), "+f"(c[1]), "+f"(c[2]), "+f"(c[3])
        : "r"(a[0]), "r"(a[1]), "r"(a[2]), "r"(a[3]), "r"(b0), "r"(b1));
}

__device__ __forceinline__ void cpa16(uint32_t dst, const void* src) {
    asm volatile("cp.async.cg.shared.global [%0], [%1], 16;" :: "r"(dst), "l"(src));
}
#define CP_COMMIT() asm volatile("cp.async.commit_group;" ::: "memory")
#define CP_WAIT1()  asm volatile("cp.async.wait_group 1;" ::: "memory")

// pack 4 fp32 -> 4 fp16 (8B)
__device__ __forceinline__ void pack4_store(float4 o, __half* p) {
    __half2 a = __floats2half2_rn(o.x, o.y);
    __half2 b = __floats2half2_rn(o.z, o.w);
    uint2 u;
    u.x = *(uint32_t*)&a;
    u.y = *(uint32_t*)&b;
    *(uint2*)p = u;
}

// ---------------- 1) token-shift mix -> fp16, + weight convert ----------------
#define MIXN ((long long)MT * CC / 4)          // 4194304 float4 units
#define WCN  (4LL * CC * CC / 4)               // 1048576 float4 units

__global__ void __launch_bounds__(256) mix_kernel(
    const float* __restrict__ x,
    const float* __restrict__ mk,
    const float* __restrict__ mv,
    const float* __restrict__ mr,
    const float* __restrict__ Wk,
    const float* __restrict__ Wv,
    const float* __restrict__ Wr,
    const float* __restrict__ Wo)
{
    long long idx = (long long)blockIdx.x * blockDim.x + threadIdx.x;
    if (idx < MIXN) {
        long long i = idx * 4;
        int c = (int)(i & (CC - 1));
        int m = (int)(i >> 10);
        int t = m & (TT - 1);

        float4 xc = *(const float4*)(x + i);
        float4 xp;
        if (t == 0) xp = make_float4(0.f, 0.f, 0.f, 0.f);
        else        xp = *(const float4*)(x + i - CC);

        float4 k4 = *(const float4*)(mk + c);
        float4 v4 = *(const float4*)(mv + c);
        float4 r4 = *(const float4*)(mr + c);

        float4 o;
        o.x = xc.x*k4.x + xp.x*(1.f-k4.x); o.y = xc.y*k4.y + xp.y*(1.f-k4.y);
        o.z = xc.z*k4.z + xp.z*(1.f-k4.z); o.w = xc.w*k4.w + xp.w*(1.f-k4.w);
        pack4_store(o, g_xk + i);
        o.x = xc.x*v4.x + xp.x*(1.f-v4.x); o.y = xc.y*v4.y + xp.y*(1.f-v4.y);
        o.z = xc.z*v4.z + xp.z*(1.f-v4.z); o.w = xc.w*v4.w + xp.w*(1.f-v4.w);
        pack4_store(o, g_xv + i);
        o.x = xc.x*r4.x + xp.x*(1.f-r4.x); o.y = xc.y*r4.y + xp.y*(1.f-r4.y);
        o.z = xc.z*r4.z + xp.z*(1.f-r4.z); o.w = xc.w*r4.w + xp.w*(1.f-r4.w);
        pack4_store(o, g_xr + i);
    } else {
        long long wi = idx - MIXN;
        if (wi >= WCN) return;
        long long i = wi * 4;
        int w = (int)(i >> 20);
        long long off = i & (CC*CC - 1);
        const float* src = (w == 0) ? Wk : (w == 1) ? Wv : (w == 2) ? Wr : Wo;
        float4 v = *(const float4*)(src + off);
        pack4_store(v, g_w + i);
    }
}

// ---------------- 2) persistent cp.async pipelined fp16 GEMM ----------------
// Proven shape: 256 thr, 8 warps (2x4), warp tile 64x32, tile 128x128, BK=64,
// 3 stages @32KB, 2 CTAs/SM. Atomic work-stealing over tiles.
// NOTE: epilogue must stay trivial (sigmoid max) — exp here spills (round 11).

#define STG_B  32768
#define GEMM_SMEM (3*STG_B)   // 98304 -> 2 CTAs/SM

#define GEMM_SETUP                                                            \
    extern __shared__ char smem[];                                            \
    __shared__ int s_tile;                                                    \
    const uint32_t sb0 = smem_u32(smem);                                      \
    const int tid = threadIdx.x;                                              \
    const int lid = tid & 31;                                                 \
    const int wid = tid >> 5;                                                 \
    const int warp_m = wid & 1;                                               \
    const int warp_n = wid >> 1;                                              \
    const int r0 = tid >> 3;                                                  \
    const int ch = tid & 7;                                                   \
    const uint32_t sdst0 = (uint32_t)(r0 * 128 + ((ch ^ (r0 & 7)) << 4));     \
    const int a_row  = warp_m * 64 + ((lid >> 3) & 1) * 8 + (lid & 7);        \
    const int a_half = (lid >> 4) & 1;                                        \
    const uint32_t a_x = (uint32_t)(a_row & 7);                               \
    const int b_row  = warp_n * 32 + (lid >> 4) * 8 + (lid & 7);              \
    const int b_half = (lid >> 3) & 1;                                        \
    const uint32_t b_x = (uint32_t)(b_row & 7);                               \
    const int er = (lid >> 2);                                                \
    const int ec = (lid & 3) * 2;

#define LOAD_STAGE(S, KC) do {                                                \
        uint32_t base = sb0 + (S) * STG_B + sdst0;                            \
        const __half* sAp = bA + (KC) * 64;                                   \
        const __half* sBp = bB + (KC) * 64;                                   \
        _Pragma("unroll")                                                     \
        for (int j = 0; j < 4; j++) {                                         \
            cpa16(base + j*4096,          sAp + (size_t)j * (32*CC));         \
            cpa16(base + 16384 + j*4096,  sBp + (size_t)j * (32*CC));         \
        }                                                                     \
    } while (0)

#define GEMM_TILE_BODY                                                        \
    float acc[4][4][4];                                                       \
    _Pragma("unroll")                                                         \
    for (int mt = 0; mt < 4; mt++)                                            \
        _Pragma("unroll")                                                     \
        for (int nt = 0; nt < 4; nt++)                                        \
            _Pragma("unroll")                                                 \
            for (int e = 0; e < 4; e++) acc[mt][nt][e] = 0.f;                 \
    const int NK = CC / 64;                                                   \
    LOAD_STAGE(0, 0); CP_COMMIT();                                            \
    LOAD_STAGE(1, 1); CP_COMMIT();                                            \
    int cs = 0;                                                               \
    int ls = 2;                                                               \
    for (int kc = 0; kc < NK; kc++) {                                         \
        CP_WAIT1();                                                           \
        __syncthreads();                                                      \
        if (kc + 2 < NK) {                                                    \
            LOAD_STAGE(ls, kc + 2);                                           \
        }                                                                     \
        CP_COMMIT();                                                          \
        const uint32_t sA = sb0 + cs * STG_B;                                 \
        const uint32_t sB = sA + 16384;                                       \
        _Pragma("unroll")                                                     \
        for (int ks = 0; ks < 4; ks++) {                                      \
            uint32_t ah[4][4];                                                \
            const uint32_t ac = ((uint32_t)(ks * 2 + a_half) ^ a_x) << 4;     \
            const uint32_t bc = ((uint32_t)(ks * 2 + b_half) ^ b_x) << 4;     \
            _Pragma("unroll")                                                 \
            for (int mt = 0; mt < 4; mt++)                                    \
                ldmx4(ah[mt], sA + (uint32_t)(a_row + mt * 16) * 128 + ac);   \
            _Pragma("unroll")                                                 \
            for (int p = 0; p < 2; p++) {                                     \
                uint32_t bh[4];                                               \
                ldmx4(bh, sB + (uint32_t)(b_row + p * 16) * 128 + bc);        \
                _Pragma("unroll")                                             \
                for (int mt = 0; mt < 4; mt++)                                \
                    _Pragma("unroll")                                         \
                    for (int n2 = 0; n2 < 2; n2++)                            \
                        mma_fp16(acc[mt][p*2 + n2], ah[mt], bh[n2*2], bh[n2*2 + 1]); \
            }                                                                 \
        }                                                                     \
        cs = (cs == 2) ? 0 : cs + 1;                                          \
        ls = (ls == 2) ? 0 : ls + 1;                                          \
    }

// -- projections: atomic tile scheduler over 3*1024 tiles; z==2 sigmoid; fp16 out --
__global__ void __launch_bounds__(256, 2) gemm_proj(
    const __half* __restrict__ A0, const __half* __restrict__ A1,
    const __half* __restrict__ A2,
    const __half* __restrict__ W,
    __half* __restrict__ C0, __half* __restrict__ C1, __half* __restrict__ C2,
    int* __restrict__ ctr)
{
    GEMM_SETUP

    for (;;) {
        if (tid == 0) s_tile = atomicAdd(ctr, 1);
        __syncthreads();
        const int t = s_tile;
        if (t >= 3 * 1024) break;

        const int z = t >> 10;
        const int rr = t & 1023;
        const int brow = rr >> 3;
        const int bcol = rr & 7;
        const __half* A = (z == 0) ? A0 : (z == 1) ? A1 : A2;
        const __half* B = W + (size_t)z * (CC * CC);
        __half* C = (z == 0) ? C0 : (z == 1) ? C1 : C2;
        const bool dosig = (z == 2);

        const __half* bA = A + ((size_t)(brow * 128 + r0)) * CC + ch * 8;
        const __half* bB = B + ((size_t)(bcol * 128 + r0)) * CC + ch * 8;

        GEMM_TILE_BODY

        #pragma unroll
        for (int mt = 0; mt < 4; mt++) {
            size_t grow = (size_t)brow * 128 + warp_m * 64 + mt * 16 + er;
            #pragma unroll
            for (int nt = 0; nt < 4; nt++) {
                int gcol = bcol * 128 + warp_n * 32 + nt * 8 + ec;
                float d0 = acc[mt][nt][0], d1 = acc[mt][nt][1];
                float d2 = acc[mt][nt][2], d3 = acc[mt][nt][3];
                if (dosig) {
                    d0 = fast_sigmoid(d0); d1 = fast_sigmoid(d1);
                    d2 = fast_sigmoid(d2); d3 = fast_sigmoid(d3);
                }
                *(__half2*)(C + grow * CC + gcol)       = __floats2half2_rn(d0, d1);
                *(__half2*)(C + (grow + 8) * CC + gcol) = __floats2half2_rn(d2, d3);
            }
        }
        __syncthreads();   // stage ring + s_tile reused next tile
    }
}

// -- output GEMM: atomic tile scheduler over 1024 tiles; fp32 out --
__global__ void __launch_bounds__(256, 2) gemm_out(
    const __half* __restrict__ Ag,
    const __half* __restrict__ Bg,
    float* __restrict__ C,
    int* __restrict__ ctr)
{
    GEMM_SETUP

    for (;;) {
        if (tid == 0) s_tile = atomicAdd(ctr, 1);
        __syncthreads();
        const int t = s_tile;
        if (t >= 1024) break;

        const int brow = t >> 3;
        const int bcol = t & 7;
        const __half* bA = Ag + ((size_t)(brow * 128 + r0)) * CC + ch * 8;
        const __half* bB = Bg + ((size_t)(bcol * 128 + r0)) * CC + ch * 8;

        GEMM_TILE_BODY

        #pragma unroll
        for (int mt = 0; mt < 4; mt++) {
            size_t grow = (size_t)brow * 128 + warp_m * 64 + mt * 16 + er;
            #pragma unroll
            for (int nt = 0; nt < 4; nt++) {
                int gcol = bcol * 128 + warp_n * 32 + nt * 8 + ec;
                *(float2*)(C + grow * CC + gcol)       = make_float2(acc[mt][nt][0], acc[mt][nt][1]);
                *(float2*)(C + (grow + 8) * CC + gcol) = make_float2(acc[mt][nt][2], acc[mt][nt][3]);
            }
        }
        __syncthreads();
    }
}

#undef LOAD_STAGE
#undef GEMM_SETUP
#undef GEMM_TILE_BODY

// ---------------- 3) WKV: chunk-parallel 3-pass scan (MUFU exp, fp16 io) ----------------
__global__ void __launch_bounds__(256) wkv_pass1(const float* __restrict__ td)
{
    int gid = blockIdx.x * 256 + threadIdx.x;
    int cp = gid & (CC/2 - 1);
    int bj = gid >> 9;
    int b = bj >> 7;
    int j = bj & (NCH - 1);
    int c = cp * 2;

    float ew0 = __expf(-__expf(td[c]));
    float ew1 = __expf(-__expf(td[c+1]));

    size_t base = ((size_t)b * TT + (size_t)j * CHUNK) * CC + c;
    const __half* kp = g_k + base;
    const __half* vp = g_v + base;

    float A0 = 0.f, B0 = 0.f, A1 = 0.f, B1 = 0.f;
    #pragma unroll 8
    for (int s = 0; s < CHUNK; s++) {
        float2 kt = __half22float2(*(const __half2*)(kp + (size_t)s * CC));
        float2 vt = __half22float2(*(const __half2*)(vp + (size_t)s * CC));
        float ek0 = __expf(kt.x);
        float ek1 = __expf(kt.y);
        A0 = fmaf(A0, ew0, ek0 * vt.x);
        B0 = fmaf(B0, ew0, ek0);
        A1 = fmaf(A1, ew1, ek1 * vt.y);
        B1 = fmaf(B1, ew1, ek1);
    }
    size_t out = ((size_t)b * NCH + j) * CC + c;
    *(float2*)(g_cA + out) = make_float2(A0, A1);
    *(float2*)(g_cB + out) = make_float2(B0, B1);
}

// combine: warp-parallel linear-recurrence scan over 128 chunks per (b,c)
__global__ void __launch_bounds__(256) wkv_combine(const float* __restrict__ td)
{
    int gw = (blockIdx.x * 256 + threadIdx.x) >> 5;   // global warp id = b*CC + c
    int lane = threadIdx.x & 31;
    int b = gw >> 10;
    int c = gw & (CC - 1);

    float w = -__expf(td[c]);
    float ewL = __expf(w * (float)CHUNK);

    size_t base = ((size_t)b * NCH + lane * 4) * CC + c;
    float ca[4], cb[4];
    #pragma unroll
    for (int i = 0; i < 4; i++) {
        ca[i] = g_cA[base + (size_t)i * CC];
        cb[i] = g_cB[base + (size_t)i * CC];
    }

    float sA = fmaf(fmaf(fmaf(ca[0], ewL, ca[1]), ewL, ca[2]), ewL, ca[3]);
    float sB = fmaf(fmaf(fmaf(cb[0], ewL, cb[1]), ewL, cb[2]), ewL, cb[3]);
    float m2 = ewL * ewL;
    float Mm = m2 * m2;      // ewL^4
    float SA = sA, SB = sB;

    #pragma unroll
    for (int d = 1; d < 32; d <<= 1) {
        float pm = __shfl_up_sync(0xFFFFFFFFu, Mm, d);
        float pa = __shfl_up_sync(0xFFFFFFFFu, SA, d);
        float pb = __shfl_up_sync(0xFFFFFFFFu, SB, d);
        if (lane >= d) {
            SA = fmaf(pa, Mm, SA);
            SB = fmaf(pb, Mm, SB);
            Mm = pm * Mm;
        }
    }

    float eA = __shfl_up_sync(0xFFFFFFFFu, SA, 1);
    float eB = __shfl_up_sync(0xFFFFFFFFu, SB, 1);
    if (lane == 0) { eA = 0.f; eB = 0.f; }

    float A = eA, Bv = eB;
    #pragma unroll
    for (int i = 0; i < 4; i++) {
        g_pA[base + (size_t)i * CC] = A;
        g_pB[base + (size_t)i * CC] = Bv;
        A = fmaf(A, ewL, ca[i]);
        Bv = fmaf(Bv, ewL, cb[i]);
    }
}

__global__ void __launch_bounds__(256) wkv_pass2(const float* __restrict__ td,
                                                 const float* __restrict__ tf)
{
    int gid = blockIdx.x * 256 + threadIdx.x;
    int cp = gid & (CC/2 - 1);
    int bj = gid >> 9;
    int b = bj >> 7;
    int j = bj & (NCH - 1);
    int c = cp * 2;

    float ew0 = __expf(-__expf(td[c]));
    float ew1 = __expf(-__expf(td[c+1]));
    float eu0 = __expf(tf[c]);
    float eu1 = __expf(tf[c+1]);

    size_t st_idx = ((size_t)b * NCH + j) * CC + c;
    float2 Ai = *(const float2*)(g_pA + st_idx);
    float2 Bi = *(const float2*)(g_pB + st_idx);
    float A0 = Ai.x, A1 = Ai.y, B0 = Bi.x, B1 = Bi.y;

    size_t base = ((size_t)b * TT + (size_t)j * CHUNK) * CC + c;
    const __half* kp = g_k + base;
    const __half* vp = g_v + base;
    const __half* sp = g_sr + base;
    __half* op = g_rw + base;

    #pragma unroll 4
    for (int s = 0; s < CHUNK; s++) {
        float2 kt = __half22float2(*(const __half2*)(kp + (size_t)s * CC));
        float2 vt = __half22float2(*(const __half2*)(vp + (size_t)s * CC));
        float2 st = __half22float2(*(const __half2*)(sp + (size_t)s * CC));
        float ek0 = __expf(kt.x);
        float ek1 = __expf(kt.y);
        float euk0 = eu0 * ek0;
        float euk1 = eu1 * ek1;
        float y0 = fmaf(euk0, vt.x, A0) * fast_rcp(B0 + euk0);
        float y1 = fmaf(euk1, vt.y, A1) * fast_rcp(B1 + euk1);
        *(__half2*)(op + (size_t)s * CC) = __floats2half2_rn(st.x * y0, st.y * y1);
        A0 = fmaf(A0, ew0, ek0 * vt.x);
        B0 = fmaf(B0, ew0, ek0);
        A1 = fmaf(A1, ew1, ek1 * vt.y);
        B1 = fmaf(B1, ew1, ek1);
    }
}

// ---------------- launch ----------------
extern "C" void kernel_launch(void* const* d_in, const int* in_sizes, int n_in,
                              void* d_out, int out_size)
{
    const float* x  = (const float*)d_in[0];
    const float* td = (const float*)d_in[1];
    const float* tf = (const float*)d_in[2];
    const float* mk = (const float*)d_in[3];
    const float* mv = (const float*)d_in[4];
    const float* mr = (const float*)d_in[5];
    const float* Wk = (const float*)d_in[6];
    const float* Wv = (const float*)d_in[7];
    const float* Wr = (const float*)d_in[8];
    const float* Wo = (const float*)d_in[9];
    float* out = (float*)d_out;

    __half *xk, *xv, *xr, *rw, *w, *p_k, *p_v, *p_sr;
    int* ctr;
    cudaGetSymbolAddress((void**)&xk, g_xk);
    cudaGetSymbolAddress((void**)&xv, g_xv);
    cudaGetSymbolAddress((void**)&xr, g_xr);
    cudaGetSymbolAddress((void**)&rw, g_rw);
    cudaGetSymbolAddress((void**)&w,  g_w);
    cudaGetSymbolAddress((void**)&p_k,  g_k);
    cudaGetSymbolAddress((void**)&p_v,  g_v);
    cudaGetSymbolAddress((void**)&p_sr, g_sr);
    cudaGetSymbolAddress((void**)&ctr,  g_ctr);

    cudaFuncSetAttribute(gemm_proj, cudaFuncAttributeMaxDynamicSharedMemorySize, GEMM_SMEM);
    cudaFuncSetAttribute(gemm_out,  cudaFuncAttributeMaxDynamicSharedMemorySize, GEMM_SMEM);

    int dev = 0, nsm = 148;
    cudaGetDevice(&dev);
    cudaDeviceGetAttribute(&nsm, cudaDevAttrMultiProcessorCount, dev);
    const int pgrid = nsm * 2;   // persistent GEMM grid: 2 CTAs/SM

    // reset tile counters (graph-capturable)
    cudaMemsetAsync(ctr, 0, 4 * sizeof(int));

    // 1) mix + weight convert (one launch)
    {
        long long total = MIXN + WCN;
        mix_kernel<<<(int)((total + 255) / 256), 256>>>(x, mk, mv, mr, Wk, Wv, Wr, Wo);
    }

    // 2) three projection GEMMs, persistent + atomic scheduler
    gemm_proj<<<pgrid, 256, GEMM_SMEM>>>(xk, xv, xr, w, p_k, p_v, p_sr, ctr + 0);

    // 3) WKV chunk-parallel scan (MUFU exp)
    {
        int n1 = BB * NCH * (CC/2);                  // 262144
        wkv_pass1<<<n1 / 256, 256>>>(td);
        wkv_combine<<<(BB * CC * 32) / 256, 256>>>(td);   // warp per (b,c)
        wkv_pass2<<<n1 / 256, 256>>>(td, tf);
    }

    // 4) output GEMM, persistent + atomic scheduler (fp32 out)
    gemm_out<<<pgrid, 256, GEMM_SMEM>>>(rw, w + 3*CC*CC, out, ctr + 1);
}

// round 15
// speedup vs baseline: 1.1391x; 1.1391x over previous
#include <cuda_runtime.h>
#include <cuda_fp16.h>
#include <cstdint>

#define BB 4
#define TT 4096
#define CC 1024
#define MT (BB*TT)          // 16384 rows
#define CHUNK 16
#define NCH (TT/CHUNK)      // 256 chunks

// ---------------- scratch (no cudaMalloc allowed) ----------------
__device__ __align__(128) __half g_xk[MT*CC];
__device__ __align__(128) __half g_xv[MT*CC];
__device__ __align__(128) __half g_xr[MT*CC];
__device__ __align__(128) __half g_rw[MT*CC];
__device__ __align__(128) __half g_w[4*CC*CC];
__device__ __align__(128) __half g_k [MT*CC];
__device__ __align__(128) __half g_v [MT*CC];
__device__ __align__(128) __half g_sr[MT*CC];
__device__ float g_cA[BB*NCH*CC];
__device__ float g_cB[BB*NCH*CC];
__device__ float g_pA[BB*NCH*CC];
__device__ float g_pB[BB*NCH*CC];

// ================= fast math (FMA-pipe, avoid MUFU) =================
__device__ __forceinline__ float fast_exp(float x) {
    float t = fmaf(x, 1.4426950408889634f, 12582912.0f);
    float n = t - 12582912.0f;
    float r = fmaf(x, 1.4426950408889634f, -n);
    float p = 1.3333558146e-3f;
    p = fmaf(p, r, 9.6181291076e-3f);
    p = fmaf(p, r, 5.5504108664e-2f);
    p = fmaf(p, r, 2.4022650696e-1f);
    p = fmaf(p, r, 6.9314718056e-1f);
    p = fmaf(p, r, 1.0f);
    int ei = (int)n;
    if (ei < -126) return 0.0f;
    if (ei > 127) ei = 127;
    return p * __int_as_float((ei + 127) << 23);
}

__device__ __forceinline__ float fast_rcp(float d) {
    float x = __int_as_float(0x7EF311C3 - __float_as_int(d));
    x = x * fmaf(-d, x, 2.0f);
    x = x * fmaf(-d, x, 2.0f);
    return x;
}

__device__ __forceinline__ float fast_sigmoid(float x) {
    return fast_rcp(1.0f + fast_exp(-x));
}

// ================= PTX helpers (arch-generic only) =================
__device__ __forceinline__ uint32_t smem_u32(const void* p) {
    uint32_t a;
    asm("{ .reg .u64 t; cvta.to.shared.u64 t, %1; cvt.u32.u64 %0, t; }" : "=r"(a) : "l"(p));
    return a;
}

__device__ __forceinline__ void ldmx4(uint32_t r[4], uint32_t addr) {
    asm volatile("ldmatrix.sync.aligned.m8n8.x4.shared.b16 {%0,%1,%2,%3}, [%4];"
        : "=r"(r[0]), "=r"(r[1]), "=r"(r[2]), "=r"(r[3]) : "r"(addr));
}

__device__ __forceinline__ void mma_fp16(float c[4], const uint32_t a[4],
                                         uint32_t b0, uint32_t b1) {
    asm volatile(
        "mma.sync.aligned.m16n8k16.row.col.f32.f16.f16.f32 "
        "{%0,%1,%2,%3}, {%4,%5,%6,%7}, {%8,%9}, {%0,%1,%2,%3};"
        : "+f"(c[0]), "+f"(c[1]), "+f"(c[2]), "+f"(c[3])
        : "r"(a[0]), "r"(a[1]), "r"(a[2]), "r"(a[3]), "r"(b0), "r"(b1));
}

__device__ __forceinline__ void cpa16(uint32_t dst, const void* src) {
    asm volatile("cp.async.cg.shared.global [%0], [%1], 16;" :: "r"(dst), "l"(src));
}
#define CP_COMMIT() asm volatile("cp.async.commit_group;" ::: "memory")
#define CP_WAIT1()  asm volatile("cp.async.wait_group 1;" ::: "memory")

// pack 4 fp32 -> 4 fp16 (8B)
__device__ __forceinline__ void pack4_store(float4 o, __half* p) {
    __half2 a = __floats2half2_rn(o.x, o.y);
    __half2 b = __floats2half2_rn(o.z, o.w);
    uint2 u;
    u.x = *(uint32_t*)&a;
    u.y = *(uint32_t*)&b;
    *(uint2*)p = u;
}

// ---------------- 0) weight convert (fp32 -> fp16) ----------------
__global__ void __launch_bounds__(256) convert_w(
    const float* __restrict__ Wk, const float* __restrict__ Wv,
    const float* __restrict__ Wr, const float* __restrict__ Wo)
{
    long long gid = (long long)blockIdx.x * 256 + threadIdx.x;
    long long i = gid * 4;
    if (i >= 4LL*CC*CC) return;
    int w = (int)(i >> 20);
    long long off = i & (CC*CC - 1);
    const float* src = (w == 0) ? Wk : (w == 1) ? Wv : (w == 2) ? Wr : Wo;
    float4 v = *(const float4*)(src + off);
    pack4_store(v, g_w + i);
}

// ---------------- 1) token-shift mix -> fp16 ----------------
__global__ void __launch_bounds__(256) mix_kernel(
    const float* __restrict__ x,
    const float* __restrict__ mk,
    const float* __restrict__ mv,
    const float* __restrict__ mr)
{
    long long idx = (long long)blockIdx.x * blockDim.x + threadIdx.x;
    long long i = idx * 4;
    if (i >= (long long)MT * CC) return;
    int c = (int)(i & (CC - 1));
    int m = (int)(i >> 10);
    int t = m & (TT - 1);

    float4 xc = *(const float4*)(x + i);
    float4 xp;
    if (t == 0) xp = make_float4(0.f, 0.f, 0.f, 0.f);
    else        xp = *(const float4*)(x + i - CC);

    float4 k4 = *(const float4*)(mk + c);
    float4 v4 = *(const float4*)(mv + c);
    float4 r4 = *(const float4*)(mr + c);

    float4 o;
    o.x = xc.x*k4.x + xp.x*(1.f-k4.x); o.y = xc.y*k4.y + xp.y*(1.f-k4.y);
    o.z = xc.z*k4.z + xp.z*(1.f-k4.z); o.w = xc.w*k4.w + xp.w*(1.f-k4.w);
    pack4_store(o, g_xk + i);
    o.x = xc.x*v4.x + xp.x*(1.f-v4.x); o.y = xc.y*v4.y + xp.y*(1.f-v4.y);
    o.z = xc.z*v4.z + xp.z*(1.f-v4.z); o.w = xc.w*v4.w + xp.w*(1.f-v4.w);
    pack4_store(o, g_xv + i);
    o.x = xc.x*r4.x + xp.x*(1.f-r4.x); o.y = xc.y*r4.y + xp.y*(1.f-r4.y);
    o.z = xc.z*r4.z + xp.z*(1.f-r4.z); o.w = xc.w*r4.w + xp.w*(1.f-r4.w);
    pack4_store(o, g_xr + i);
}

// ---------------- 2) persistent cp.async pipelined fp16 GEMM ----------------
// Proven shape: 256 thr, 8 warps (2x4), warp tile 64x32, tile 128x128, BK=64,
// 3 stages @32KB, 2 CTAs/SM, persistent static striding over tiles.
// NOTE: epilogue must stay trivial (sigmoid max) — exp here spills (round 11).

#define STG_B  32768
#define GEMM_SMEM (3*STG_B)   // 98304 -> 2 CTAs/SM

#define GEMM_SETUP                                                            \
    extern __shared__ char smem[];                                            \
    const uint32_t sb0 = smem_u32(smem);                                      \
    const int tid = threadIdx.x;                                              \
    const int lid = tid & 31;                                                 \
    const int wid = tid >> 5;                                                 \
    const int warp_m = wid & 1;                                               \
    const int warp_n = wid >> 1;                                              \
    const int r0 = tid >> 3;                                                  \
    const int ch = tid & 7;                                                   \
    const uint32_t sdst0 = (uint32_t)(r0 * 128 + ((ch ^ (r0 & 7)) << 4));     \
    const int a_row  = warp_m * 64 + ((lid >> 3) & 1) * 8 + (lid & 7);        \
    const int a_half = (lid >> 4) & 1;                                        \
    const uint32_t a_x = (uint32_t)(a_row & 7);                               \
    const int b_row  = warp_n * 32 + (lid >> 4) * 8 + (lid & 7);              \
    const int b_half = (lid >> 3) & 1;                                        \
    const uint32_t b_x = (uint32_t)(b_row & 7);                               \
    const int er = (lid >> 2);                                                \
    const int ec = (lid & 3) * 2;

#define LOAD_STAGE(S, KC) do {                                                \
        uint32_t base = sb0 + (S) * STG_B + sdst0;                            \
        const __half* sAp = bA + (KC) * 64;                                   \
        const __half* sBp = bB + (KC) * 64;                                   \
        _Pragma("unroll")                                                     \
        for (int j = 0; j < 4; j++) {                                         \
            cpa16(base + j*4096,          sAp + (size_t)j * (32*CC));         \
            cpa16(base + 16384 + j*4096,  sBp + (size_t)j * (32*CC));         \
        }                                                                     \
    } while (0)

#define GEMM_TILE_BODY                                                        \
    float acc[4][4][4];                                                       \
    _Pragma("unroll")                                                         \
    for (int mt = 0; mt < 4; mt++)                                            \
        _Pragma("unroll")                                                     \
        for (int nt = 0; nt < 4; nt++)                                        \
            _Pragma("unroll")                                                 \
            for (int e = 0; e < 4; e++) acc[mt][nt][e] = 0.f;                 \
    const int NK = CC / 64;                                                   \
    LOAD_STAGE(0, 0); CP_COMMIT();                                            \
    LOAD_STAGE(1, 1); CP_COMMIT();                                            \
    int cs = 0;                                                               \
    int ls = 2;                                                               \
    for (int kc = 0; kc < NK; kc++) {                                         \
        CP_WAIT1();                                                           \
        __syncthreads();                                                      \
        if (kc + 2 < NK) {                                                    \
            LOAD_STAGE(ls, kc + 2);                                           \
        }                                                                     \
        CP_COMMIT();                                                          \
        const uint32_t sA = sb0 + cs * STG_B;                                 \
        const uint32_t sB = sA + 16384;                                       \
        _Pragma("unroll")                                                     \
        for (int ks = 0; ks < 4; ks++) {                                      \
            uint32_t ah[4][4];                                                \
            const uint32_t ac = ((uint32_t)(ks * 2 + a_half) ^ a_x) << 4;     \
            const uint32_t bc = ((uint32_t)(ks * 2 + b_half) ^ b_x) << 4;     \
            _Pragma("unroll")                                                 \
            for (int mt = 0; mt < 4; mt++)                                    \
                ldmx4(ah[mt], sA + (uint32_t)(a_row + mt * 16) * 128 + ac);   \
            _Pragma("unroll")                                                 \
            for (int p = 0; p < 2; p++) {                                     \
                uint32_t bh[4];                                               \
                ldmx4(bh, sB + (uint32_t)(b_row + p * 16) * 128 + bc);        \
                _Pragma("unroll")                                             \
                for (int mt = 0; mt < 4; mt++)                                \
                    _Pragma("unroll")                                         \
                    for (int n2 = 0; n2 < 2; n2++)                            \
                        mma_fp16(acc[mt][p*2 + n2], ah[mt], bh[n2*2], bh[n2*2 + 1]); \
            }                                                                 \
        }                                                                     \
        cs = (cs == 2) ? 0 : cs + 1;                                          \
        ls = (ls == 2) ? 0 : ls + 1;                                          \
    }

// -- projections: persistent over 3*1024 tiles; z==2 applies sigmoid; fp16 out --
__global__ void __launch_bounds__(256, 2) gemm_proj(
    const __half* __restrict__ A0, const __half* __restrict__ A1,
    const __half* __restrict__ A2,
    const __half* __restrict__ W,
    __half* __restrict__ C0, __half* __restrict__ C1, __half* __restrict__ C2)
{
    GEMM_SETUP

    for (int t = blockIdx.x; t < 3 * 1024; t += gridDim.x) {
        const int z = t >> 10;
        const int rr = t & 1023;
        const int brow = rr >> 3;
        const int bcol = rr & 7;
        const __half* A = (z == 0) ? A0 : (z == 1) ? A1 : A2;
        const __half* B = W + (size_t)z * (CC * CC);
        __half* C = (z == 0) ? C0 : (z == 1) ? C1 : C2;
        const bool dosig = (z == 2);

        const __half* bA = A + ((size_t)(brow * 128 + r0)) * CC + ch * 8;
        const __half* bB = B + ((size_t)(bcol * 128 + r0)) * CC + ch * 8;

        GEMM_TILE_BODY

        #pragma unroll
        for (int mt = 0; mt < 4; mt++) {
            size_t grow = (size_t)brow * 128 + warp_m * 64 + mt * 16 + er;
            #pragma unroll
            for (int nt = 0; nt < 4; nt++) {
                int gcol = bcol * 128 + warp_n * 32 + nt * 8 + ec;
                float d0 = acc[mt][nt][0], d1 = acc[mt][nt][1];
                float d2 = acc[mt][nt][2], d3 = acc[mt][nt][3];
                if (dosig) {
                    d0 = fast_sigmoid(d0); d1 = fast_sigmoid(d1);
                    d2 = fast_sigmoid(d2); d3 = fast_sigmoid(d3);
                }
                *(__half2*)(C + grow * CC + gcol)       = __floats2half2_rn(d0, d1);
                *(__half2*)(C + (grow + 8) * CC + gcol) = __floats2half2_rn(d2, d3);
            }
        }
        __syncthreads();   // stage ring reused next tile
    }
}

// -- output GEMM: persistent over 1024 tiles; fp32 out --
__global__ void __launch_bounds__(256, 2) gemm_out(
    const __half* __restrict__ Ag,
    const __half* __restrict__ Bg,
    float* __restrict__ C)
{
    GEMM_SETUP

    for (int t = blockIdx.x; t < 1024; t += gridDim.x) {
        const int brow = t >> 3;
        const int bcol = t & 7;
        const __half* bA = Ag + ((size_t)(brow * 128 + r0)) * CC + ch * 8;
        const __half* bB = Bg + ((size_t)(bcol * 128 + r0)) * CC + ch * 8;

        GEMM_TILE_BODY

        #pragma unroll
        for (int mt = 0; mt < 4; mt++) {
            size_t grow = (size_t)brow * 128 + warp_m * 64 + mt * 16 + er;
            #pragma unroll
            for (int nt = 0; nt < 4; nt++) {
                int gcol = bcol * 128 + warp_n * 32 + nt * 8 + ec;
                *(float2*)(C + grow * CC + gcol)       = make_float2(acc[mt][nt][0], acc[mt][nt][1]);
                *(float2*)(C + (grow + 8) * CC + gcol) = make_float2(acc[mt][nt][2], acc[mt][nt][3]);
            }
        }
        __syncthreads();
    }
}

#undef LOAD_STAGE
#undef GEMM_SETUP
#undef GEMM_TILE_BODY

// ---------------- 3) WKV: chunk-parallel 3-pass scan (fp16 io, 2 ch/thread) ----------------
__global__ void __launch_bounds__(256) wkv_pass1(const float* __restrict__ td)
{
    int gid = blockIdx.x * 256 + threadIdx.x;        // over BB*NCH*(CC/2)
    int cp = gid & (CC/2 - 1);                        // channel pair
    int bj = gid >> 9;
    int b = bj >> 8;                                  // NCH = 256
    int j = bj & (NCH - 1);
    int c = cp * 2;

    float ew0 = fast_exp(-fast_exp(td[c]));
    float ew1 = fast_exp(-fast_exp(td[c+1]));

    size_t base = ((size_t)b * TT + (size_t)j * CHUNK) * CC + c;
    const __half* kp = g_k + base;
    const __half* vp = g_v + base;

    float A0 = 0.f, B0 = 0.f, A1 = 0.f, B1 = 0.f;
    #pragma unroll
    for (int s = 0; s < CHUNK; s++) {
        float2 kt = __half22float2(*(const __half2*)(kp + (size_t)s * CC));
        float2 vt = __half22float2(*(const __half2*)(vp + (size_t)s * CC));
        float ek0 = fast_exp(kt.x);
        float ek1 = fast_exp(kt.y);
        A0 = fmaf(A0, ew0, ek0 * vt.x);
        B0 = fmaf(B0, ew0, ek0);
        A1 = fmaf(A1, ew1, ek1 * vt.y);
        B1 = fmaf(B1, ew1, ek1);
    }
    size_t out = ((size_t)b * NCH + j) * CC + c;
    *(float2*)(g_cA + out) = make_float2(A0, A1);
    *(float2*)(g_cB + out) = make_float2(B0, B1);
}

// combine: warp-parallel linear-recurrence scan over 256 chunks per (b,c)
__global__ void __launch_bounds__(256) wkv_combine(const float* __restrict__ td)
{
    int gw = (blockIdx.x * 256 + threadIdx.x) >> 5;   // global warp id = b*CC + c
    int lane = threadIdx.x & 31;
    int b = gw >> 10;
    int c = gw & (CC - 1);

    float w = -fast_exp(td[c]);
    float ewL = fast_exp(w * (float)CHUNK);

    // lane owns chunks j in [lane*8, lane*8+8)
    size_t base = ((size_t)b * NCH + lane * 8) * CC + c;
    float ca[8], cb[8];
    #pragma unroll
    for (int i = 0; i < 8; i++) {
        ca[i] = g_cA[base + (size_t)i * CC];
        cb[i] = g_cB[base + (size_t)i * CC];
    }

    // local segment sums: s = sum_i ca[i] * ewL^(7-i), m = ewL^8
    float sA = ca[0], sB = cb[0];
    #pragma unroll
    for (int i = 1; i < 8; i++) {
        sA = fmaf(sA, ewL, ca[i]);
        sB = fmaf(sB, ewL, cb[i]);
    }
    float m2 = ewL * ewL;
    float m4 = m2 * m2;
    float Mm = m4 * m4;      // ewL^8
    float SA = sA, SB = sB;

    // inclusive Kogge-Stone scan: (earlier)∘(current)
    #pragma unroll
    for (int d = 1; d < 32; d <<= 1) {
        float pm = __shfl_up_sync(0xFFFFFFFFu, Mm, d);
        float pa = __shfl_up_sync(0xFFFFFFFFu, SA, d);
        float pb = __shfl_up_sync(0xFFFFFFFFu, SB, d);
        if (lane >= d) {
            SA = fmaf(pa, Mm, SA);
            SB = fmaf(pb, Mm, SB);
            Mm = pm * Mm;
        }
    }

    // exclusive
    float eA = __shfl_up_sync(0xFFFFFFFFu, SA, 1);
    float eB = __shfl_up_sync(0xFFFFFFFFu, SB, 1);
    if (lane == 0) { eA = 0.f; eB = 0.f; }

    float A = eA, Bv = eB;
    #pragma unroll
    for (int i = 0; i < 8; i++) {
        g_pA[base + (size_t)i * CC] = A;
        g_pB[base + (size_t)i * CC] = Bv;
        A = fmaf(A, ewL, ca[i]);
        Bv = fmaf(Bv, ewL, cb[i]);
    }
}

__global__ void __launch_bounds__(256) wkv_pass2(const float* __restrict__ td,
                                                 const float* __restrict__ tf)
{
    int gid = blockIdx.x * 256 + threadIdx.x;
    int cp = gid & (CC/2 - 1);
    int bj = gid >> 9;
    int b = bj >> 8;                                  // NCH = 256
    int j = bj & (NCH - 1);
    int c = cp * 2;

    float ew0 = fast_exp(-fast_exp(td[c]));
    float ew1 = fast_exp(-fast_exp(td[c+1]));
    float eu0 = fast_exp(tf[c]);
    float eu1 = fast_exp(tf[c+1]);

    size_t st_idx = ((size_t)b * NCH + j) * CC + c;
    float2 Ai = *(const float2*)(g_pA + st_idx);
    float2 Bi = *(const float2*)(g_pB + st_idx);
    float A0 = Ai.x, A1 = Ai.y, B0 = Bi.x, B1 = Bi.y;

    size_t base = ((size_t)b * TT + (size_t)j * CHUNK) * CC + c;
    const __half* kp = g_k + base;
    const __half* vp = g_v + base;
    const __half* sp = g_sr + base;
    __half* op = g_rw + base;

    #pragma unroll
    for (int s = 0; s < CHUNK; s++) {
        float2 kt = __half22float2(*(const __half2*)(kp + (size_t)s * CC));
        float2 vt = __half22float2(*(const __half2*)(vp + (size_t)s * CC));
        float2 st = __half22float2(*(const __half2*)(sp + (size_t)s * CC));
        float ek0 = fast_exp(kt.x);
        float ek1 = fast_exp(kt.y);
        float euk0 = eu0 * ek0;
        float euk1 = eu1 * ek1;
        float y0 = fmaf(euk0, vt.x, A0) * fast_rcp(B0 + euk0);
        float y1 = fmaf(euk1, vt.y, A1) * fast_rcp(B1 + euk1);
        *(__half2*)(op + (size_t)s * CC) = __floats2half2_rn(st.x * y0, st.y * y1);
        A0 = fmaf(A0, ew0, ek0 * vt.x);
        B0 = fmaf(B0, ew0, ek0);
        A1 = fmaf(A1, ew1, ek1 * vt.y);
        B1 = fmaf(B1, ew1, ek1);
    }
}

// ---------------- launch ----------------
extern "C" void kernel_launch(void* const* d_in, const int* in_sizes, int n_in,
                              void* d_out, int out_size)
{
    const float* x  = (const float*)d_in[0];
    const float* td = (const float*)d_in[1];
    const float* tf = (const float*)d_in[2];
    const float* mk = (const float*)d_in[3];
    const float* mv = (const float*)d_in[4];
    const float* mr = (const float*)d_in[5];
    const float* Wk = (const float*)d_in[6];
    const float* Wv = (const float*)d_in[7];
    const float* Wr = (const float*)d_in[8];
    const float* Wo = (const float*)d_in[9];
    float* out = (float*)d_out;

    __half *xk, *xv, *xr, *rw, *w, *p_k, *p_v, *p_sr;
    cudaGetSymbolAddress((void**)&xk, g_xk);
    cudaGetSymbolAddress((void**)&xv, g_xv);
    cudaGetSymbolAddress((void**)&xr, g_xr);
    cudaGetSymbolAddress((void**)&rw, g_rw);
    cudaGetSymbolAddress((void**)&w,  g_w);
    cudaGetSymbolAddress((void**)&p_k,  g_k);
    cudaGetSymbolAddress((void**)&p_v,  g_v);
    cudaGetSymbolAddress((void**)&p_sr, g_sr);

    cudaFuncSetAttribute(gemm_proj, cudaFuncAttributeMaxDynamicSharedMemorySize, GEMM_SMEM);
    cudaFuncSetAttribute(gemm_out,  cudaFuncAttributeMaxDynamicSharedMemorySize, GEMM_SMEM);

    int dev = 0, nsm = 148;
    cudaGetDevice(&dev);
    cudaDeviceGetAttribute(&nsm, cudaDevAttrMultiProcessorCount, dev);
    const int pgrid = nsm * 2;   // persistent GEMM grid: 2 CTAs/SM

    // 0) weight convert
    convert_w<<<(4*CC*CC/4 + 255) / 256, 256>>>(Wk, Wv, Wr, Wo);

    // 1) mix -> fp16
    {
        long long n4 = (long long)MT * CC / 4;
        mix_kernel<<<(int)((n4 + 255) / 256), 256>>>(x, mk, mv, mr);
    }

    // 2) three projection GEMMs, persistent (fp16 out, sigmoid on z==2)
    gemm_proj<<<pgrid, 256, GEMM_SMEM>>>(xk, xv, xr, w, p_k, p_v, p_sr);

    // 3) WKV chunk-parallel scan (CHUNK=16, 2 channels per thread)
    {
        int n1 = BB * NCH * (CC/2);                  // 524288
        wkv_pass1<<<n1 / 256, 256>>>(td);
        wkv_combine<<<(BB * CC * 32) / 256, 256>>>(td);   // warp per (b,c)
        wkv_pass2<<<n1 / 256, 256>>>(td, tf);
    }

    // 4) output GEMM, persistent (fp32 out)
    gemm_out<<<pgrid, 256, GEMM_SMEM>>>(rw, w + 3*CC*CC, out);
}

// round 16
// speedup vs baseline: 1.1631x; 1.0211x over previous
#include <cuda_runtime.h>
#include <cuda_fp16.h>
#include <cstdint>

#define BB 4
#define TT 4096
#define CC 1024
#define MT (BB*TT)          // 16384 rows
#define CHUNK 32
#define NCH (TT/CHUNK)      // 128 chunks

// ---------------- scratch (no cudaMalloc allowed) ----------------
__device__ __align__(128) __half g_xk[MT*CC];
__device__ __align__(128) __half g_xv[MT*CC];
__device__ __align__(128) __half g_xr[MT*CC];
__device__ __align__(128) __half g_rw[MT*CC];
__device__ __align__(128) __half g_w[4*CC*CC];
__device__ __align__(128) __half g_k [MT*CC];
__device__ __align__(128) __half g_v [MT*CC];
__device__ __align__(128) __half g_sr[MT*CC];
__device__ float g_cA[BB*NCH*CC];
__device__ float g_cB[BB*NCH*CC];
__device__ float g_pA[BB*NCH*CC];
__device__ float g_pB[BB*NCH*CC];

// ================= fast math (FMA-pipe, avoid MUFU) =================
__device__ __forceinline__ float fast_exp(float x) {
    float t = fmaf(x, 1.4426950408889634f, 12582912.0f);
    float n = t - 12582912.0f;
    float r = fmaf(x, 1.4426950408889634f, -n);
    float p = 1.3333558146e-3f;
    p = fmaf(p, r, 9.6181291076e-3f);
    p = fmaf(p, r, 5.5504108664e-2f);
    p = fmaf(p, r, 2.4022650696e-1f);
    p = fmaf(p, r, 6.9314718056e-1f);
    p = fmaf(p, r, 1.0f);
    int ei = (int)n;
    if (ei < -126) return 0.0f;
    if (ei > 127) ei = 127;
    return p * __int_as_float((ei + 127) << 23);
}

__device__ __forceinline__ float fast_rcp(float d) {
    float x = __int_as_float(0x7EF311C3 - __float_as_int(d));
    x = x * fmaf(-d, x, 2.0f);
    x = x * fmaf(-d, x, 2.0f);
    return x;
}

__device__ __forceinline__ float fast_sigmoid(float x) {
    return fast_rcp(1.0f + fast_exp(-x));
}

// ================= PTX helpers (arch-generic only) =================
__device__ __forceinline__ uint32_t smem_u32(const void* p) {
    uint32_t a;
    asm("{ .reg .u64 t; cvta.to.shared.u64 t, %1; cvt.u32.u64 %0, t; }" : "=r"(a) : "l"(p));
    return a;
}

__device__ __forceinline__ void ldmx4(uint32_t r[4], uint32_t addr) {
    asm volatile("ldmatrix.sync.aligned.m8n8.x4.shared.b16 {%0,%1,%2,%3}, [%4];"
        : "=r"(r[0]), "=r"(r[1]), "=r"(r[2]), "=r"(r[3]) : "r"(addr));
}

__device__ __forceinline__ void mma_fp16(float c[4], const uint32_t a[4],
                                         uint32_t b0, uint32_t b1) {
    asm volatile(
        "mma.sync.aligned.m16n8k16.row.col.f32.f16.f16.f32 "
        "{%0,%1,%2,%3}, {%4,%5,%6,%7}, {%8,%9}, {%0,%1,%2,%3};"
        : "+f"(c[0]), "+f"(c[1]), "+f"(c[2]), "+f"(c[3])
        : "r"(a[0]), "r"(a[1]), "r"(a[2]), "r"(a[3]), "r"(b0), "r"(b1));
}

__device__ __forceinline__ void cpa16(uint32_t dst, const void* src) {
    asm volatile("cp.async.cg.shared.global [%0], [%1], 16;" :: "r"(dst), "l"(src));
}
#define CP_COMMIT() asm volatile("cp.async.commit_group;" ::: "memory")
#define CP_WAIT1()  asm volatile("cp.async.wait_group 1;" ::: "memory")

// pack 4 fp32 -> 4 fp16 (8B)
__device__ __forceinline__ void pack4_store(float4 o, __half* p) {
    __half2 a = __floats2half2_rn(o.x, o.y);
    __half2 b = __floats2half2_rn(o.z, o.w);
    uint2 u;
    u.x = *(uint32_t*)&a;
    u.y = *(uint32_t*)&b;
    *(uint2*)p = u;
}

// ---------------- 1) token-shift mix -> fp16, + weight convert (one launch) ----------------
#define MIXN ((long long)MT * CC / 4)          // 4194304 float4 units
#define WCN  (4LL * CC * CC / 4)               // 1048576 float4 units

__global__ void __launch_bounds__(256) mix_kernel(
    const float* __restrict__ x,
    const float* __restrict__ mk,
    const float* __restrict__ mv,
    const float* __restrict__ mr,
    const float* __restrict__ Wk,
    const float* __restrict__ Wv,
    const float* __restrict__ Wr,
    const float* __restrict__ Wo)
{
    long long idx = (long long)blockIdx.x * blockDim.x + threadIdx.x;
    if (idx < MIXN) {
        long long i = idx * 4;
        int c = (int)(i & (CC - 1));
        int m = (int)(i >> 10);
        int t = m & (TT - 1);

        float4 xc = *(const float4*)(x + i);
        float4 xp;
        if (t == 0) xp = make_float4(0.f, 0.f, 0.f, 0.f);
        else        xp = *(const float4*)(x + i - CC);

        float4 k4 = *(const float4*)(mk + c);
        float4 v4 = *(const float4*)(mv + c);
        float4 r4 = *(const float4*)(mr + c);

        float4 o;
        o.x = xc.x*k4.x + xp.x*(1.f-k4.x); o.y = xc.y*k4.y + xp.y*(1.f-k4.y);
        o.z = xc.z*k4.z + xp.z*(1.f-k4.z); o.w = xc.w*k4.w + xp.w*(1.f-k4.w);
        pack4_store(o, g_xk + i);
        o.x = xc.x*v4.x + xp.x*(1.f-v4.x); o.y = xc.y*v4.y + xp.y*(1.f-v4.y);
        o.z = xc.z*v4.z + xp.z*(1.f-v4.z); o.w = xc.w*v4.w + xp.w*(1.f-v4.w);
        pack4_store(o, g_xv + i);
        o.x = xc.x*r4.x + xp.x*(1.f-r4.x); o.y = xc.y*r4.y + xp.y*(1.f-r4.y);
        o.z = xc.z*r4.z + xp.z*(1.f-r4.z); o.w = xc.w*r4.w + xp.w*(1.f-r4.w);
        pack4_store(o, g_xr + i);
    } else {
        long long wi = idx - MIXN;
        if (wi >= WCN) return;
        long long i = wi * 4;
        int w = (int)(i >> 20);
        long long off = i & (CC*CC - 1);
        const float* src = (w == 0) ? Wk : (w == 1) ? Wv : (w == 2) ? Wr : Wo;
        float4 v = *(const float4*)(src + off);
        pack4_store(v, g_w + i);
    }
}

// ---------------- 2) persistent cp.async pipelined fp16 GEMM ----------------
// Proven shape: 256 thr, 8 warps (2x4), warp tile 64x32, tile 128x128, BK=64,
// 3 stages @32KB, 2 CTAs/SM, persistent static striding over tiles.
// NOTE: epilogue must stay trivial (sigmoid max) — exp here spills (round 11).

#define STG_B  32768
#define GEMM_SMEM (3*STG_B)   // 98304 -> 2 CTAs/SM

#define GEMM_SETUP                                                            \
    extern __shared__ char smem[];                                            \
    const uint32_t sb0 = smem_u32(smem);                                      \
    const int tid = threadIdx.x;                                              \
    const int lid = tid & 31;                                                 \
    const int wid = tid >> 5;                                                 \
    const int warp_m = wid & 1;                                               \
    const int warp_n = wid >> 1;                                              \
    const int r0 = tid >> 3;                                                  \
    const int ch = tid & 7;                                                   \
    const uint32_t sdst0 = (uint32_t)(r0 * 128 + ((ch ^ (r0 & 7)) << 4));     \
    const int a_row  = warp_m * 64 + ((lid >> 3) & 1) * 8 + (lid & 7);        \
    const int a_half = (lid >> 4) & 1;                                        \
    const uint32_t a_x = (uint32_t)(a_row & 7);                               \
    const int b_row  = warp_n * 32 + (lid >> 4) * 8 + (lid & 7);              \
    const int b_half = (lid >> 3) & 1;                                        \
    const uint32_t b_x = (uint32_t)(b_row & 7);                               \
    const int er = (lid >> 2);                                                \
    const int ec = (lid & 3) * 2;

#define LOAD_STAGE(S, KC) do {                                                \
        uint32_t base = sb0 + (S) * STG_B + sdst0;                            \
        const __half* sAp = bA + (KC) * 64;                                   \
        const __half* sBp = bB + (KC) * 64;                                   \
        _Pragma("unroll")                                                     \
        for (int j = 0; j < 4; j++) {                                         \
            cpa16(base + j*4096,          sAp + (size_t)j * (32*CC));         \
            cpa16(base + 16384 + j*4096,  sBp + (size_t)j * (32*CC));         \
        }                                                                     \
    } while (0)

#define GEMM_TILE_BODY                                                        \
    float acc[4][4][4];                                                       \
    _Pragma("unroll")                                                         \
    for (int mt = 0; mt < 4; mt++)                                            \
        _Pragma("unroll")                                                     \
        for (int nt = 0; nt < 4; nt++)                                        \
            _Pragma("unroll")                                                 \
            for (int e = 0; e < 4; e++) acc[mt][nt][e] = 0.f;                 \
    const int NK = CC / 64;                                                   \
    LOAD_STAGE(0, 0); CP_COMMIT();                                            \
    LOAD_STAGE(1, 1); CP_COMMIT();                                            \
    int cs = 0;                                                               \
    int ls = 2;                                                               \
    for (int kc = 0; kc < NK; kc++) {                                         \
        CP_WAIT1();                                                           \
        __syncthreads();                                                      \
        if (kc + 2 < NK) {                                                    \
            LOAD_STAGE(ls, kc + 2);                                           \
        }                                                                     \
        CP_COMMIT();                                                          \
        const uint32_t sA = sb0 + cs * STG_B;                                 \
        const uint32_t sB = sA + 16384;                                       \
        _Pragma("unroll")                                                     \
        for (int ks = 0; ks < 4; ks++) {                                      \
            uint32_t ah[4][4];                                                \
            const uint32_t ac = ((uint32_t)(ks * 2 + a_half) ^ a_x) << 4;     \
            const uint32_t bc = ((uint32_t)(ks * 2 + b_half) ^ b_x) << 4;     \
            _Pragma("unroll")                                                 \
            for (int mt = 0; mt < 4; mt++)                                    \
                ldmx4(ah[mt], sA + (uint32_t)(a_row + mt * 16) * 128 + ac);   \
            _Pragma("unroll")                                                 \
            for (int p = 0; p < 2; p++) {                                     \
                uint32_t bh[4];                                               \
                ldmx4(bh, sB + (uint32_t)(b_row + p * 16) * 128 + bc);        \
                _Pragma("unroll")                                             \
                for (int mt = 0; mt < 4; mt++)                                \
                    _Pragma("unroll")                                         \
                    for (int n2 = 0; n2 < 2; n2++)                            \
                        mma_fp16(acc[mt][p*2 + n2], ah[mt], bh[n2*2], bh[n2*2 + 1]); \
            }                                                                 \
        }                                                                     \
        cs = (cs == 2) ? 0 : cs + 1;                                          \
        ls = (ls == 2) ? 0 : ls + 1;                                          \
    }

// -- projections: persistent over 3*1024 tiles; z==2 applies sigmoid; fp16 out --
__global__ void __launch_bounds__(256, 2) gemm_proj(
    const __half* __restrict__ A0, const __half* __restrict__ A1,
    const __half* __restrict__ A2,
    const __half* __restrict__ W,
    __half* __restrict__ C0, __half* __restrict__ C1, __half* __restrict__ C2)
{
    GEMM_SETUP

    for (int t = blockIdx.x; t < 3 * 1024; t += gridDim.x) {
        const int z = t >> 10;
        const int rr = t & 1023;
        const int brow = rr >> 3;
        const int bcol = rr & 7;
        const __half* A = (z == 0) ? A0 : (z == 1) ? A1 : A2;
        const __half* B = W + (size_t)z * (CC * CC);
        __half* C = (z == 0) ? C0 : (z == 1) ? C1 : C2;
        const bool dosig = (z == 2);

        const __half* bA = A + ((size_t)(brow * 128 + r0)) * CC + ch * 8;
        const __half* bB = B + ((size_t)(bcol * 128 + r0)) * CC + ch * 8;

        GEMM_TILE_BODY

        #pragma unroll
        for (int mt = 0; mt < 4; mt++) {
            size_t grow = (size_t)brow * 128 + warp_m * 64 + mt * 16 + er;
            #pragma unroll
            for (int nt = 0; nt < 4; nt++) {
                int gcol = bcol * 128 + warp_n * 32 + nt * 8 + ec;
                float d0 = acc[mt][nt][0], d1 = acc[mt][nt][1];
                float d2 = acc[mt][nt][2], d3 = acc[mt][nt][3];
                if (dosig) {
                    d0 = fast_sigmoid(d0); d1 = fast_sigmoid(d1);
                    d2 = fast_sigmoid(d2); d3 = fast_sigmoid(d3);
                }
                *(__half2*)(C + grow * CC + gcol)       = __floats2half2_rn(d0, d1);
                *(__half2*)(C + (grow + 8) * CC + gcol) = __floats2half2_rn(d2, d3);
            }
        }
        __syncthreads();   // stage ring reused next tile
    }
}

// -- output GEMM: persistent over 1024 tiles; fp32 out --
__global__ void __launch_bounds__(256, 2) gemm_out(
    const __half* __restrict__ Ag,
    const __half* __restrict__ Bg,
    float* __restrict__ C)
{
    GEMM_SETUP

    for (int t = blockIdx.x; t < 1024; t += gridDim.x) {
        const int brow = t >> 3;
        const int bcol = t & 7;
        const __half* bA = Ag + ((size_t)(brow * 128 + r0)) * CC + ch * 8;
        const __half* bB = Bg + ((size_t)(bcol * 128 + r0)) * CC + ch * 8;

        GEMM_TILE_BODY

        #pragma unroll
        for (int mt = 0; mt < 4; mt++) {
            size_t grow = (size_t)brow * 128 + warp_m * 64 + mt * 16 + er;
            #pragma unroll
            for (int nt = 0; nt < 4; nt++) {
                int gcol = bcol * 128 + warp_n * 32 + nt * 8 + ec;
                *(float2*)(C + grow * CC + gcol)       = make_float2(acc[mt][nt][0], acc[mt][nt][1]);
                *(float2*)(C + (grow + 8) * CC + gcol) = make_float2(acc[mt][nt][2], acc[mt][nt][3]);
            }
        }
        __syncthreads();
    }
}

#undef LOAD_STAGE
#undef GEMM_SETUP
#undef GEMM_TILE_BODY

// ---------------- 3) WKV: chunk-parallel 3-pass scan (fp16 io, 2 ch/thread) ----------------
__global__ void __launch_bounds__(256) wkv_pass1(const float* __restrict__ td)
{
    int gid = blockIdx.x * 256 + threadIdx.x;        // over BB*NCH*(CC/2)
    int cp = gid & (CC/2 - 1);                        // channel pair
    int bj = gid >> 9;
    int b = bj >> 7;                                  // NCH = 128
    int j = bj & (NCH - 1);
    int c = cp * 2;

    float ew0 = fast_exp(-fast_exp(td[c]));
    float ew1 = fast_exp(-fast_exp(td[c+1]));

    size_t base = ((size_t)b * TT + (size_t)j * CHUNK) * CC + c;
    const __half* kp = g_k + base;
    const __half* vp = g_v + base;

    float A0 = 0.f, B0 = 0.f, A1 = 0.f, B1 = 0.f;
    #pragma unroll 8
    for (int s = 0; s < CHUNK; s++) {
        float2 kt = __half22float2(*(const __half2*)(kp + (size_t)s * CC));
        float2 vt = __half22float2(*(const __half2*)(vp + (size_t)s * CC));
        float ek0 = fast_exp(kt.x);
        float ek1 = fast_exp(kt.y);
        A0 = fmaf(A0, ew0, ek0 * vt.x);
        B0 = fmaf(B0, ew0, ek0);
        A1 = fmaf(A1, ew1, ek1 * vt.y);
        B1 = fmaf(B1, ew1, ek1);
    }
    size_t out = ((size_t)b * NCH + j) * CC + c;
    *(float2*)(g_cA + out) = make_float2(A0, A1);
    *(float2*)(g_cB + out) = make_float2(B0, B1);
}

// combine: warp-parallel linear-recurrence scan over 128 chunks per (b,c)
__global__ void __launch_bounds__(256) wkv_combine(const float* __restrict__ td)
{
    int gw = (blockIdx.x * 256 + threadIdx.x) >> 5;   // global warp id = b*CC + c
    int lane = threadIdx.x & 31;
    int b = gw >> 10;
    int c = gw & (CC - 1);

    float w = -fast_exp(td[c]);
    float ewL = fast_exp(w * (float)CHUNK);

    // lane owns chunks j in [lane*4, lane*4+4)
    size_t base = ((size_t)b * NCH + lane * 4) * CC + c;
    float ca[4], cb[4];
    #pragma unroll
    for (int i = 0; i < 4; i++) {
        ca[i] = g_cA[base + (size_t)i * CC];
        cb[i] = g_cB[base + (size_t)i * CC];
    }

    // local segment sums: s = weighted sum, m = ewL^4
    float sA = fmaf(fmaf(fmaf(ca[0], ewL, ca[1]), ewL, ca[2]), ewL, ca[3]);
    float sB = fmaf(fmaf(fmaf(cb[0], ewL, cb[1]), ewL, cb[2]), ewL, cb[3]);
    float m2 = ewL * ewL;
    float Mm = m2 * m2;      // ewL^4
    float SA = sA, SB = sB;

    // inclusive Kogge-Stone scan: (earlier)∘(current)
    #pragma unroll
    for (int d = 1; d < 32; d <<= 1) {
        float pm = __shfl_up_sync(0xFFFFFFFFu, Mm, d);
        float pa = __shfl_up_sync(0xFFFFFFFFu, SA, d);
        float pb = __shfl_up_sync(0xFFFFFFFFu, SB, d);
        if (lane >= d) {
            SA = fmaf(pa, Mm, SA);
            SB = fmaf(pb, Mm, SB);
            Mm = pm * Mm;
        }
    }

    // exclusive
    float eA = __shfl_up_sync(0xFFFFFFFFu, SA, 1);
    float eB = __shfl_up_sync(0xFFFFFFFFu, SB, 1);
    if (lane == 0) { eA = 0.f; eB = 0.f; }

    float A = eA, Bv = eB;
    #pragma unroll
    for (int i = 0; i < 4; i++) {
        g_pA[base + (size_t)i * CC] = A;
        g_pB[base + (size_t)i * CC] = Bv;
        A = fmaf(A, ewL, ca[i]);
        Bv = fmaf(Bv, ewL, cb[i]);
    }
}

__global__ void __launch_bounds__(256) wkv_pass2(const float* __restrict__ td,
                                                 const float* __restrict__ tf)
{
    int gid = blockIdx.x * 256 + threadIdx.x;
    int cp = gid & (CC/2 - 1);
    int bj = gid >> 9;
    int b = bj >> 7;                                  // NCH = 128
    int j = bj & (NCH - 1);
    int c = cp * 2;

    float ew0 = fast_exp(-fast_exp(td[c]));
    float ew1 = fast_exp(-fast_exp(td[c+1]));
    float eu0 = fast_exp(tf[c]);
    float eu1 = fast_exp(tf[c+1]);

    size_t st_idx = ((size_t)b * NCH + j) * CC + c;
    float2 Ai = *(const float2*)(g_pA + st_idx);
    float2 Bi = *(const float2*)(g_pB + st_idx);
    float A0 = Ai.x, A1 = Ai.y, B0 = Bi.x, B1 = Bi.y;

    size_t base = ((size_t)b * TT + (size_t)j * CHUNK) * CC + c;
    const __half* kp = g_k + base;
    const __half* vp = g_v + base;
    const __half* sp = g_sr + base;
    __half* op = g_rw + base;

    #pragma unroll 4
    for (int s = 0; s < CHUNK; s++) {
        float2 kt = __half22float2(*(const __half2*)(kp + (size_t)s * CC));
        float2 vt = __half22float2(*(const __half2*)(vp + (size_t)s * CC));
        float2 st = __half22float2(*(const __half2*)(sp + (size_t)s * CC));
        float ek0 = fast_exp(kt.x);
        float ek1 = fast_exp(kt.y);
        float euk0 = eu0 * ek0;
        float euk1 = eu1 * ek1;
        float y0 = fmaf(euk0, vt.x, A0) * fast_rcp(B0 + euk0);
        float y1 = fmaf(euk1, vt.y, A1) * fast_rcp(B1 + euk1);
        *(__half2*)(op + (size_t)s * CC) = __floats2half2_rn(st.x * y0, st.y * y1);
        A0 = fmaf(A0, ew0, ek0 * vt.x);
        B0 = fmaf(B0, ew0, ek0);
        A1 = fmaf(A1, ew1, ek1 * vt.y);
        B1 = fmaf(B1, ew1, ek1);
    }
}

// ---------------- launch ----------------
extern "C" void kernel_launch(void* const* d_in, const int* in_sizes, int n_in,
                              void* d_out, int out_size)
{
    const float* x  = (const float*)d_in[0];
    const float* td = (const float*)d_in[1];
    const float* tf = (const float*)d_in[2];
    const float* mk = (const float*)d_in[3];
    const float* mv = (const float*)d_in[4];
    const float* mr = (const float*)d_in[5];
    const float* Wk = (const float*)d_in[6];
    const float* Wv = (const float*)d_in[7];
    const float* Wr = (const float*)d_in[8];
    const float* Wo = (const float*)d_in[9];
    float* out = (float*)d_out;

    __half *xk, *xv, *xr, *rw, *w, *p_k, *p_v, *p_sr;
    cudaGetSymbolAddress((void**)&xk, g_xk);
    cudaGetSymbolAddress((void**)&xv, g_xv);
    cudaGetSymbolAddress((void**)&xr, g_xr);
    cudaGetSymbolAddress((void**)&rw, g_rw);
    cudaGetSymbolAddress((void**)&w,  g_w);
    cudaGetSymbolAddress((void**)&p_k,  g_k);
    cudaGetSymbolAddress((void**)&p_v,  g_v);
    cudaGetSymbolAddress((void**)&p_sr, g_sr);

    cudaFuncSetAttribute(gemm_proj, cudaFuncAttributeMaxDynamicSharedMemorySize, GEMM_SMEM);
    cudaFuncSetAttribute(gemm_out,  cudaFuncAttributeMaxDynamicSharedMemorySize, GEMM_SMEM);

    int dev = 0, nsm = 148;
    cudaGetDevice(&dev);
    cudaDeviceGetAttribute(&nsm, cudaDevAttrMultiProcessorCount, dev);
    const int pgrid = nsm * 2;   // persistent GEMM grid: 2 CTAs/SM

    // 1) mix + weight convert (one launch)
    {
        long long total = MIXN + WCN;
        mix_kernel<<<(int)((total + 255) / 256), 256>>>(x, mk, mv, mr, Wk, Wv, Wr, Wo);
    }

    // 2) three projection GEMMs, persistent (fp16 out, sigmoid on z==2)
    gemm_proj<<<pgrid, 256, GEMM_SMEM>>>(xk, xv, xr, w, p_k, p_v, p_sr);

    // 3) WKV chunk-parallel scan (CHUNK=32, 2 channels per thread)
    {
        int n1 = BB * NCH * (CC/2);                  // 262144
        wkv_pass1<<<n1 / 256, 256>>>(td);
        wkv_combine<<<(BB * CC * 32) / 256, 256>>>(td);   // warp per (b,c)
        wkv_pass2<<<n1 / 256, 256>>>(td, tf);
    }

    // 4) output GEMM, persistent (fp32 out)
    gemm_out<<<pgrid, 256, GEMM_SMEM>>>(rw, w + 3*CC*CC, out);
}

// round 17
// speedup vs baseline: 1.1755x; 1.0106x over previous
#include <cuda_runtime.h>
#include <cuda_fp16.h>
#include <cstdint>

#define BB 4
#define TT 4096
#define CC 1024
#define MT (BB*TT)          // 16384 rows
#define CHUNK 32
#define NCH (TT/CHUNK)      // 128 chunks

// ---------------- scratch (no cudaMalloc allowed) ----------------
__device__ __align__(128) __half g_xk[MT*CC];
__device__ __align__(128) __half g_xv[MT*CC];
__device__ __align__(128) __half g_xr[MT*CC];
__device__ __align__(128) __half g_rw[MT*CC];
__device__ __align__(128) __half g_w[4*CC*CC];
__device__ __align__(128) __half g_k [MT*CC];
__device__ __align__(128) __half g_v [MT*CC];
__device__ __align__(128) __half g_sr[MT*CC];
__device__ __align__(128) float2 g_cAB[BB*NCH*CC];   // {A,B} per channel
__device__ __align__(128) float2 g_pAB[BB*NCH*CC];   // prefix {A,B} per channel

// ================= fast math (FMA-pipe, avoid MUFU) =================
__device__ __forceinline__ float fast_exp(float x) {
    float t = fmaf(x, 1.4426950408889634f, 12582912.0f);
    float n = t - 12582912.0f;
    float r = fmaf(x, 1.4426950408889634f, -n);
    float p = 1.3333558146e-3f;
    p = fmaf(p, r, 9.6181291076e-3f);
    p = fmaf(p, r, 5.5504108664e-2f);
    p = fmaf(p, r, 2.4022650696e-1f);
    p = fmaf(p, r, 6.9314718056e-1f);
    p = fmaf(p, r, 1.0f);
    int ei = (int)n;
    if (ei < -126) return 0.0f;
    if (ei > 127) ei = 127;
    return p * __int_as_float((ei + 127) << 23);
}

__device__ __forceinline__ float fast_rcp(float d) {
    float x = __int_as_float(0x7EF311C3 - __float_as_int(d));
    x = x * fmaf(-d, x, 2.0f);
    x = x * fmaf(-d, x, 2.0f);
    return x;
}

__device__ __forceinline__ float fast_sigmoid(float x) {
    return fast_rcp(1.0f + fast_exp(-x));
}

// ================= PTX helpers (arch-generic only) =================
__device__ __forceinline__ uint32_t smem_u32(const void* p) {
    uint32_t a;
    asm("{ .reg .u64 t; cvta.to.shared.u64 t, %1; cvt.u32.u64 %0, t; }" : "=r"(a) : "l"(p));
    return a;
}

__device__ __forceinline__ void ldmx4(uint32_t r[4], uint32_t addr) {
    asm volatile("ldmatrix.sync.aligned.m8n8.x4.shared.b16 {%0,%1,%2,%3}, [%4];"
        : "=r"(r[0]), "=r"(r[1]), "=r"(r[2]), "=r"(r[3]) : "r"(addr));
}

__device__ __forceinline__ void mma_fp16(float c[4], const uint32_t a[4],
                                         uint32_t b0, uint32_t b1) {
    asm volatile(
        "mma.sync.aligned.m16n8k16.row.col.f32.f16.f16.f32 "
        "{%0,%1,%2,%3}, {%4,%5,%6,%7}, {%8,%9}, {%0,%1,%2,%3};"
        : "+f"(c[0]), "+f"(c[1]), "+f"(c[2]), "+f"(c[3])
        : "r"(a[0]), "r"(a[1]), "r"(a[2]), "r"(a[3]), "r"(b0), "r"(b1));
}

__device__ __forceinline__ void cpa16(uint32_t dst, const void* src) {
    asm volatile("cp.async.cg.shared.global [%0], [%1], 16;" :: "r"(dst), "l"(src));
}
#define CP_COMMIT() asm volatile("cp.async.commit_group;" ::: "memory")
#define CP_WAIT1()  asm volatile("cp.async.wait_group 1;" ::: "memory")

// pack 4 fp32 -> 4 fp16 (8B)
__device__ __forceinline__ void pack4_store(float4 o, __half* p) {
    __half2 a = __floats2half2_rn(o.x, o.y);
    __half2 b = __floats2half2_rn(o.z, o.w);
    uint2 u;
    u.x = *(uint32_t*)&a;
    u.y = *(uint32_t*)&b;
    *(uint2*)p = u;
}

// ---------------- 1) token-shift mix -> fp16, + weight convert (one launch) ----------------
#define MIXN ((long long)MT * CC / 4)          // 4194304 float4 units
#define WCN  (4LL * CC * CC / 4)               // 1048576 float4 units

__global__ void __launch_bounds__(256) mix_kernel(
    const float* __restrict__ x,
    const float* __restrict__ mk,
    const float* __restrict__ mv,
    const float* __restrict__ mr,
    const float* __restrict__ Wk,
    const float* __restrict__ Wv,
    const float* __restrict__ Wr,
    const float* __restrict__ Wo)
{
    long long idx = (long long)blockIdx.x * blockDim.x + threadIdx.x;
    if (idx < MIXN) {
        long long i = idx * 4;
        int c = (int)(i & (CC - 1));
        int m = (int)(i >> 10);
        int t = m & (TT - 1);

        float4 xc = *(const float4*)(x + i);
        float4 xp;
        if (t == 0) xp = make_float4(0.f, 0.f, 0.f, 0.f);
        else        xp = *(const float4*)(x + i - CC);

        float4 k4 = *(const float4*)(mk + c);
        float4 v4 = *(const float4*)(mv + c);
        float4 r4 = *(const float4*)(mr + c);

        float4 o;
        o.x = xc.x*k4.x + xp.x*(1.f-k4.x); o.y = xc.y*k4.y + xp.y*(1.f-k4.y);
        o.z = xc.z*k4.z + xp.z*(1.f-k4.z); o.w = xc.w*k4.w + xp.w*(1.f-k4.w);
        pack4_store(o, g_xk + i);
        o.x = xc.x*v4.x + xp.x*(1.f-v4.x); o.y = xc.y*v4.y + xp.y*(1.f-v4.y);
        o.z = xc.z*v4.z + xp.z*(1.f-v4.z); o.w = xc.w*v4.w + xp.w*(1.f-v4.w);
        pack4_store(o, g_xv + i);
        o.x = xc.x*r4.x + xp.x*(1.f-r4.x); o.y = xc.y*r4.y + xp.y*(1.f-r4.y);
        o.z = xc.z*r4.z + xp.z*(1.f-r4.z); o.w = xc.w*r4.w + xp.w*(1.f-r4.w);
        pack4_store(o, g_xr + i);
    } else {
        long long wi = idx - MIXN;
        if (wi >= WCN) return;
        long long i = wi * 4;
        int w = (int)(i >> 20);
        long long off = i & (CC*CC - 1);
        const float* src = (w == 0) ? Wk : (w == 1) ? Wv : (w == 2) ? Wr : Wo;
        float4 v = *(const float4*)(src + off);
        pack4_store(v, g_w + i);
    }
}

// ---------------- 2) persistent cp.async pipelined fp16 GEMM ----------------
// Proven shape: 256 thr, 8 warps (2x4), warp tile 64x32, tile 128x128, BK=64,
// 3 stages @32KB, 2 CTAs/SM, persistent static striding over tiles.
// NOTE: epilogue must stay trivial (sigmoid max) — exp here spills (round 11).

#define STG_B  32768
#define GEMM_SMEM (3*STG_B)   // 98304 -> 2 CTAs/SM

#define GEMM_SETUP                                                            \
    extern __shared__ char smem[];                                            \
    const uint32_t sb0 = smem_u32(smem);                                      \
    const int tid = threadIdx.x;                                              \
    const int lid = tid & 31;                                                 \
    const int wid = tid >> 5;                                                 \
    const int warp_m = wid & 1;                                               \
    const int warp_n = wid >> 1;                                              \
    const int r0 = tid >> 3;                                                  \
    const int ch = tid & 7;                                                   \
    const uint32_t sdst0 = (uint32_t)(r0 * 128 + ((ch ^ (r0 & 7)) << 4));     \
    const int a_row  = warp_m * 64 + ((lid >> 3) & 1) * 8 + (lid & 7);        \
    const int a_half = (lid >> 4) & 1;                                        \
    const uint32_t a_x = (uint32_t)(a_row & 7);                               \
    const int b_row  = warp_n * 32 + (lid >> 4) * 8 + (lid & 7);              \
    const int b_half = (lid >> 3) & 1;                                        \
    const uint32_t b_x = (uint32_t)(b_row & 7);                               \
    const int er = (lid >> 2);                                                \
    const int ec = (lid & 3) * 2;

#define LOAD_STAGE(S, KC) do {                                                \
        uint32_t base = sb0 + (S) * STG_B + sdst0;                            \
        const __half* sAp = bA + (KC) * 64;                                   \
        const __half* sBp = bB + (KC) * 64;                                   \
        _Pragma("unroll")                                                     \
        for (int j = 0; j < 4; j++) {                                         \
            cpa16(base + j*4096,          sAp + (size_t)j * (32*CC));         \
            cpa16(base + 16384 + j*4096,  sBp + (size_t)j * (32*CC));         \
        }                                                                     \
    } while (0)

#define GEMM_TILE_BODY                                                        \
    float acc[4][4][4];                                                       \
    _Pragma("unroll")                                                         \
    for (int mt = 0; mt < 4; mt++)                                            \
        _Pragma("unroll")                                                     \
        for (int nt = 0; nt < 4; nt++)                                        \
            _Pragma("unroll")                                                 \
            for (int e = 0; e < 4; e++) acc[mt][nt][e] = 0.f;                 \
    const int NK = CC / 64;                                                   \
    LOAD_STAGE(0, 0); CP_COMMIT();                                            \
    LOAD_STAGE(1, 1); CP_COMMIT();                                            \
    int cs = 0;                                                               \
    int ls = 2;                                                               \
    for (int kc = 0; kc < NK; kc++) {                                         \
        CP_WAIT1();                                                           \
        __syncthreads();                                                      \
        if (kc + 2 < NK) {                                                    \
            LOAD_STAGE(ls, kc + 2);                                           \
        }                                                                     \
        CP_COMMIT();                                                          \
        const uint32_t sA = sb0 + cs * STG_B;                                 \
        const uint32_t sB = sA + 16384;                                       \
        _Pragma("unroll")                                                     \
        for (int ks = 0; ks < 4; ks++) {                                      \
            uint32_t ah[4][4];                                                \
            const uint32_t ac = ((uint32_t)(ks * 2 + a_half) ^ a_x) << 4;     \
            const uint32_t bc = ((uint32_t)(ks * 2 + b_half) ^ b_x) << 4;     \
            _Pragma("unroll")                                                 \
            for (int mt = 0; mt < 4; mt++)                                    \
                ldmx4(ah[mt], sA + (uint32_t)(a_row + mt * 16) * 128 + ac);   \
            _Pragma("unroll")                                                 \
            for (int p = 0; p < 2; p++) {                                     \
                uint32_t bh[4];                                               \
                ldmx4(bh, sB + (uint32_t)(b_row + p * 16) * 128 + bc);        \
                _Pragma("unroll")                                             \
                for (int mt = 0; mt < 4; mt++)                                \
                    _Pragma("unroll")                                         \
                    for (int n2 = 0; n2 < 2; n2++)                            \
                        mma_fp16(acc[mt][p*2 + n2], ah[mt], bh[n2*2], bh[n2*2 + 1]); \
            }                                                                 \
        }                                                                     \
        cs = (cs == 2) ? 0 : cs + 1;                                          \
        ls = (ls == 2) ? 0 : ls + 1;                                          \
    }

// -- projections: persistent over 3*1024 tiles; z==2 applies sigmoid; fp16 out --
__global__ void __launch_bounds__(256, 2) gemm_proj(
    const __half* __restrict__ A0, const __half* __restrict__ A1,
    const __half* __restrict__ A2,
    const __half* __restrict__ W,
    __half* __restrict__ C0, __half* __restrict__ C1, __half* __restrict__ C2)
{
    GEMM_SETUP

    for (int t = blockIdx.x; t < 3 * 1024; t += gridDim.x) {
        const int z = t >> 10;
        const int rr = t & 1023;
        const int brow = rr >> 3;
        const int bcol = rr & 7;
        const __half* A = (z == 0) ? A0 : (z == 1) ? A1 : A2;
        const __half* B = W + (size_t)z * (CC * CC);
        __half* C = (z == 0) ? C0 : (z == 1) ? C1 : C2;
        const bool dosig = (z == 2);

        const __half* bA = A + ((size_t)(brow * 128 + r0)) * CC + ch * 8;
        const __half* bB = B + ((size_t)(bcol * 128 + r0)) * CC + ch * 8;

        GEMM_TILE_BODY

        #pragma unroll
        for (int mt = 0; mt < 4; mt++) {
            size_t grow = (size_t)brow * 128 + warp_m * 64 + mt * 16 + er;
            #pragma unroll
            for (int nt = 0; nt < 4; nt++) {
                int gcol = bcol * 128 + warp_n * 32 + nt * 8 + ec;
                float d0 = acc[mt][nt][0], d1 = acc[mt][nt][1];
                float d2 = acc[mt][nt][2], d3 = acc[mt][nt][3];
                if (dosig) {
                    d0 = fast_sigmoid(d0); d1 = fast_sigmoid(d1);
                    d2 = fast_sigmoid(d2); d3 = fast_sigmoid(d3);
                }
                *(__half2*)(C + grow * CC + gcol)       = __floats2half2_rn(d0, d1);
                *(__half2*)(C + (grow + 8) * CC + gcol) = __floats2half2_rn(d2, d3);
            }
        }
        __syncthreads();   // stage ring reused next tile
    }
}

// -- output GEMM: persistent over 1024 tiles; fp32 out --
__global__ void __launch_bounds__(256, 2) gemm_out(
    const __half* __restrict__ Ag,
    const __half* __restrict__ Bg,
    float* __restrict__ C)
{
    GEMM_SETUP

    for (int t = blockIdx.x; t < 1024; t += gridDim.x) {
        const int brow = t >> 3;
        const int bcol = t & 7;
        const __half* bA = Ag + ((size_t)(brow * 128 + r0)) * CC + ch * 8;
        const __half* bB = Bg + ((size_t)(bcol * 128 + r0)) * CC + ch * 8;

        GEMM_TILE_BODY

        #pragma unroll
        for (int mt = 0; mt < 4; mt++) {
            size_t grow = (size_t)brow * 128 + warp_m * 64 + mt * 16 + er;
            #pragma unroll
            for (int nt = 0; nt < 4; nt++) {
                int gcol = bcol * 128 + warp_n * 32 + nt * 8 + ec;
                *(float2*)(C + grow * CC + gcol)       = make_float2(acc[mt][nt][0], acc[mt][nt][1]);
                *(float2*)(C + (grow + 8) * CC + gcol) = make_float2(acc[mt][nt][2], acc[mt][nt][3]);
            }
        }
        __syncthreads();
    }
}

#undef LOAD_STAGE
#undef GEMM_SETUP
#undef GEMM_TILE_BODY

// ---------------- 3) WKV: chunk-parallel 3-pass scan (fp16 io, AoS {A,B} state) ----------------
__global__ void __launch_bounds__(256) wkv_pass1(const float* __restrict__ td)
{
    int gid = blockIdx.x * 256 + threadIdx.x;        // over BB*NCH*(CC/2)
    int cp = gid & (CC/2 - 1);                        // channel pair
    int bj = gid >> 9;
    int b = bj >> 7;                                  // NCH = 128
    int j = bj & (NCH - 1);
    int c = cp * 2;

    float ew0 = fast_exp(-fast_exp(td[c]));
    float ew1 = fast_exp(-fast_exp(td[c+1]));

    size_t base = ((size_t)b * TT + (size_t)j * CHUNK) * CC + c;
    const __half* kp = g_k + base;
    const __half* vp = g_v + base;

    float A0 = 0.f, B0 = 0.f, A1 = 0.f, B1 = 0.f;
    #pragma unroll 8
    for (int s = 0; s < CHUNK; s++) {
        float2 kt = __half22float2(*(const __half2*)(kp + (size_t)s * CC));
        float2 vt = __half22float2(*(const __half2*)(vp + (size_t)s * CC));
        float ek0 = fast_exp(kt.x);
        float ek1 = fast_exp(kt.y);
        A0 = fmaf(A0, ew0, ek0 * vt.x);
        B0 = fmaf(B0, ew0, ek0);
        A1 = fmaf(A1, ew1, ek1 * vt.y);
        B1 = fmaf(B1, ew1, ek1);
    }
    size_t out = ((size_t)b * NCH + j) * CC + c;      // float2 index, c even
    *(float4*)(g_cAB + out) = make_float4(A0, B0, A1, B1);
}

// combine: warp-parallel linear-recurrence scan over 128 chunks per (b,c)
__global__ void __launch_bounds__(256) wkv_combine(const float* __restrict__ td)
{
    int gw = (blockIdx.x * 256 + threadIdx.x) >> 5;   // global warp id = b*CC + c
    int lane = threadIdx.x & 31;
    int b = gw >> 10;
    int c = gw & (CC - 1);

    float w = -fast_exp(td[c]);
    float ewL = fast_exp(w * (float)CHUNK);

    // lane owns chunks j in [lane*4, lane*4+4); one 8B load per chunk
    size_t base = ((size_t)b * NCH + lane * 4) * CC + c;
    float ca[4], cb[4];
    #pragma unroll
    for (int i = 0; i < 4; i++) {
        float2 v = g_cAB[base + (size_t)i * CC];
        ca[i] = v.x;
        cb[i] = v.y;
    }

    // local segment sums: s = weighted sum, m = ewL^4
    float sA = fmaf(fmaf(fmaf(ca[0], ewL, ca[1]), ewL, ca[2]), ewL, ca[3]);
    float sB = fmaf(fmaf(fmaf(cb[0], ewL, cb[1]), ewL, cb[2]), ewL, cb[3]);
    float m2 = ewL * ewL;
    float Mm = m2 * m2;      // ewL^4
    float SA = sA, SB = sB;

    // inclusive Kogge-Stone scan: (earlier)∘(current)
    #pragma unroll
    for (int d = 1; d < 32; d <<= 1) {
        float pm = __shfl_up_sync(0xFFFFFFFFu, Mm, d);
        float pa = __shfl_up_sync(0xFFFFFFFFu, SA, d);
        float pb = __shfl_up_sync(0xFFFFFFFFu, SB, d);
        if (lane >= d) {
            SA = fmaf(pa, Mm, SA);
            SB = fmaf(pb, Mm, SB);
            Mm = pm * Mm;
        }
    }

    // exclusive
    float eA = __shfl_up_sync(0xFFFFFFFFu, SA, 1);
    float eB = __shfl_up_sync(0xFFFFFFFFu, SB, 1);
    if (lane == 0) { eA = 0.f; eB = 0.f; }

    float A = eA, Bv = eB;
    #pragma unroll
    for (int i = 0; i < 4; i++) {
        g_pAB[base + (size_t)i * CC] = make_float2(A, Bv);
        A = fmaf(A, ewL, ca[i]);
        Bv = fmaf(Bv, ewL, cb[i]);
    }
}

__global__ void __launch_bounds__(256) wkv_pass2(const float* __restrict__ td,
                                                 const float* __restrict__ tf)
{
    int gid = blockIdx.x * 256 + threadIdx.x;
    int cp = gid & (CC/2 - 1);
    int bj = gid >> 9;
    int b = bj >> 7;                                  // NCH = 128
    int j = bj & (NCH - 1);
    int c = cp * 2;

    float ew0 = fast_exp(-fast_exp(td[c]));
    float ew1 = fast_exp(-fast_exp(td[c+1]));
    float eu0 = fast_exp(tf[c]);
    float eu1 = fast_exp(tf[c+1]);

    size_t st_idx = ((size_t)b * NCH + j) * CC + c;   // float2 index, c even
    float4 P = *(const float4*)(g_pAB + st_idx);
    float A0 = P.x, B0 = P.y, A1 = P.z, B1 = P.w;

    size_t base = ((size_t)b * TT + (size_t)j * CHUNK) * CC + c;
    const __half* kp = g_k + base;
    const __half* vp = g_v + base;
    const __half* sp = g_sr + base;
    __half* op = g_rw + base;

    #pragma unroll 4
    for (int s = 0; s < CHUNK; s++) {
        float2 kt = __half22float2(*(const __half2*)(kp + (size_t)s * CC));
        float2 vt = __half22float2(*(const __half2*)(vp + (size_t)s * CC));
        float2 st = __half22float2(*(const __half2*)(sp + (size_t)s * CC));
        float ek0 = fast_exp(kt.x);
        float ek1 = fast_exp(kt.y);
        float euk0 = eu0 * ek0;
        float euk1 = eu1 * ek1;
        float y0 = fmaf(euk0, vt.x, A0) * fast_rcp(B0 + euk0);
        float y1 = fmaf(euk1, vt.y, A1) * fast_rcp(B1 + euk1);
        *(__half2*)(op + (size_t)s * CC) = __floats2half2_rn(st.x * y0, st.y * y1);
        A0 = fmaf(A0, ew0, ek0 * vt.x);
        B0 = fmaf(B0, ew0, ek0);
        A1 = fmaf(A1, ew1, ek1 * vt.y);
        B1 = fmaf(B1, ew1, ek1);
    }
}

// ---------------- launch ----------------
extern "C" void kernel_launch(void* const* d_in, const int* in_sizes, int n_in,
                              void* d_out, int out_size)
{
    const float* x  = (const float*)d_in[0];
    const float* td = (const float*)d_in[1];
    const float* tf = (const float*)d_in[2];
    const float* mk = (const float*)d_in[3];
    const float* mv = (const float*)d_in[4];
    const float* mr = (const float*)d_in[5];
    const float* Wk = (const float*)d_in[6];
    const float* Wv = (const float*)d_in[7];
    const float* Wr = (const float*)d_in[8];
    const float* Wo = (const float*)d_in[9];
    float* out = (float*)d_out;

    __half *xk, *xv, *xr, *rw, *w, *p_k, *p_v, *p_sr;
    cudaGetSymbolAddress((void**)&xk, g_xk);
    cudaGetSymbolAddress((void**)&xv, g_xv);
    cudaGetSymbolAddress((void**)&xr, g_xr);
    cudaGetSymbolAddress((void**)&rw, g_rw);
    cudaGetSymbolAddress((void**)&w,  g_w);
    cudaGetSymbolAddress((void**)&p_k,  g_k);
    cudaGetSymbolAddress((void**)&p_v,  g_v);
    cudaGetSymbolAddress((void**)&p_sr, g_sr);

    cudaFuncSetAttribute(gemm_proj, cudaFuncAttributeMaxDynamicSharedMemorySize, GEMM_SMEM);
    cudaFuncSetAttribute(gemm_out,  cudaFuncAttributeMaxDynamicSharedMemorySize, GEMM_SMEM);

    int dev = 0, nsm = 148;
    cudaGetDevice(&dev);
    cudaDeviceGetAttribute(&nsm, cudaDevAttrMultiProcessorCount, dev);
    const int pgrid = nsm * 2;   // persistent GEMM grid: 2 CTAs/SM

    // 1) mix + weight convert (one launch)
    {
        long long total = MIXN + WCN;
        mix_kernel<<<(int)((total + 255) / 256), 256>>>(x, mk, mv, mr, Wk, Wv, Wr, Wo);
    }

    // 2) three projection GEMMs, persistent (fp16 out, sigmoid on z==2)
    gemm_proj<<<pgrid, 256, GEMM_SMEM>>>(xk, xv, xr, w, p_k, p_v, p_sr);

    // 3) WKV chunk-parallel scan (CHUNK=32, 2 channels per thread)
    {
        int n1 = BB * NCH * (CC/2);                  // 262144
        wkv_pass1<<<n1 / 256, 256>>>(td);
        wkv_combine<<<(BB * CC * 32) / 256, 256>>>(td);   // warp per (b,c)
        wkv_pass2<<<n1 / 256, 256>>>(td, tf);
    }

    // 4) output GEMM, persistent (fp32 out)
    gemm_out<<<pgrid, 256, GEMM_SMEM>>>(rw, w + 3*CC*CC, out);
}